// round 3
// baseline (speedup 1.0000x reference)
#include <cuda_runtime.h>
#include <math.h>

// Problem constants
#define SEQ   1000
#define IND   100
#define POOLW 10
#define HID   64
#define OUTD  5
#define NB    16
#define BATCH 65536

// Tiling: 64 batch rows per CTA; 128 threads; thread t -> row (t&63), out-half (t>>6)
#define BM     64
#define KC     64             // k-chunk = 4 i's x 16 basis
#define NCHUNK 25             // 1600 / 64
#define NTHR   128

// smem (floats):
//   xp  [100][64]   offset 0     (6400)  -- reused for c2s (5120) in phase 3
//   sA  [64][68]    offset 6400  (4352)  -- reused for reduction scratch in phase 3
#define OFF_XP 0
#define OFF_SA 6400
#define SMEM_FLOATS (6400 + 64*68)
#define SMEM_BYTES  (SMEM_FLOATS * 4)

__device__ __forceinline__ unsigned long long pk2(float lo, float hi) {
    unsigned long long r;
    asm("mov.b64 %0, {%1,%2};" : "=l"(r) : "f"(lo), "f"(hi));
    return r;
}
__device__ __forceinline__ void upk2(unsigned long long v, float& lo, float& hi) {
    asm("mov.b64 {%0,%1}, %2;" : "=f"(lo), "=f"(hi) : "l"(v));
}
__device__ __forceinline__ void fma2(unsigned long long& d, unsigned long long a, unsigned long long b) {
    asm("fma.rn.f32x2 %0, %1, %2, %0;" : "+l"(d) : "l"(a), "l"(b));
}

extern __shared__ float smem[];

__global__ __launch_bounds__(NTHR, 3)
void kan_fused_kernel(const float* __restrict__ x,
                      const float* __restrict__ c1,    // [64][100][16] = [64][1600]
                      const float* __restrict__ c2,    // [5][64][16]   = [5][1024]
                      const float* __restrict__ centers,
                      float* __restrict__ out)         // [BATCH][5]
{
    const int t   = threadIdx.x;
    const int blk = blockIdx.x;

    float* xp  = smem + OFF_XP;   // [i][row]
    float* sA  = smem + OFF_SA;   // [k][o], pad 68
    float* c2s = smem + OFF_XP;   // phase 3: flat copy of c2 (5120 floats)
    float* red = smem + OFF_SA;   // phase 3: reduction scratch

    const float K2 = -0.5f / 0.36f;

    float ctr[NB];
    #pragma unroll
    for (int n = 0; n < NB; n++) ctr[n] = __ldg(centers + n);

    // ---------------- Phase 1: pool 1000 -> 100 ----------------
    const float* xblk = x + (size_t)blk * BM * SEQ;
    for (int p = t; p < BM * IND; p += NTHR) {
        int row = p / IND;
        int i   = p - row * IND;
        const float* xr = xblk + row * SEQ + i * POOLW;
        float s = 0.f;
        #pragma unroll
        for (int m = 0; m < POOLW; m++) s += __ldg(xr + m);
        xp[i * BM + row] = s * (1.0f / POOLW);
    }
    __syncthreads();

    const int r  = t & 63;   // batch row within CTA
    const int oh = t >> 6;   // output half: o in [32*oh, 32*oh+32)

    // per-row stats (two-pass, ddof=1, eps outside sqrt) — pair does it redundantly
    float mu = 0.f;
    #pragma unroll 10
    for (int i = 0; i < IND; i++) mu += xp[i * BM + r];
    mu *= (1.0f / IND);
    float var = 0.f;
    #pragma unroll 10
    for (int i = 0; i < IND; i++) { float d = xp[i * BM + r] - mu; var += d * d; }
    var *= (1.0f / (IND - 1));
    const float sc = 1.0f / (sqrtf(var) + 1e-6f);

    // ---------------- Phase 2: basis (registers) + GEMM1 with broadcast A ----------------
    unsigned long long acc[16];
    #pragma unroll
    for (int m = 0; m < 16; m++) acc[m] = 0ull;

    for (int ch = 0; ch < NCHUNK; ch++) {
        __syncthreads();   // previous chunk's sA reads complete

        // stage sA[k][o] = c1[o][ch*64 + k]  (coalesced along k across lanes)
        {
            int k  = t & 63;
            int o0 = t >> 6;               // 0 or 1
            const float* cp = c1 + (size_t)ch * KC + k;
            #pragma unroll 8
            for (int j = 0; j < 32; j++) {
                int o = o0 + 2 * j;
                sA[k * 68 + o] = __ldg(cp + (size_t)o * 1600);
            }
        }
        __syncthreads();

        #pragma unroll 1
        for (int ii = 0; ii < 4; ii++) {
            float xn = (xp[(ch * 4 + ii) * BM + r] - mu) * sc;
            float br[NB];
            #pragma unroll
            for (int n = 0; n < NB; n++) {
                float d = xn - ctr[n];
                br[n] = __expf(K2 * d * d);
            }
            #pragma unroll 4
            for (int n = 0; n < NB; n++) {
                unsigned long long b2 = pk2(br[n], br[n]);
                const ulonglong2* ar =
                    (const ulonglong2*)(sA + (ii * NB + n) * 68 + oh * 32);
                #pragma unroll
                for (int j = 0; j < 8; j++) {
                    ulonglong2 a = ar[j];           // broadcast LDS.128 (all lanes same addr)
                    fma2(acc[2 * j],     b2, a.x);
                    fma2(acc[2 * j + 1], b2, a.y);
                }
            }
        }
    }

    // ---------------- epilogue: tanh into registers ----------------
    float h[32];
    #pragma unroll
    for (int m = 0; m < 16; m++) upk2(acc[m], h[2 * m], h[2 * m + 1]);
    #pragma unroll 8
    for (int j = 0; j < 32; j++) h[j] = tanhf(h[j]);

    __syncthreads();   // all sA/xp reads done before reuse

    // pair-exchange stats for row norm over 64 values
    float ps = 0.f, pq = 0.f;
    #pragma unroll 8
    for (int j = 0; j < 32; j++) { ps += h[j]; pq += h[j] * h[j]; }
    red[t * 2]     = ps;
    red[t * 2 + 1] = pq;

    // stage c2 into smem (xp region is dead now)
    for (int e = t; e < OUTD * HID * NB; e += NTHR) c2s[e] = __ldg(c2 + e);
    __syncthreads();

    float sm = red[(t ^ 64) * 2]     + ps;
    float sq = red[(t ^ 64) * 2 + 1] + pq;
    float m2 = sm * (1.0f / HID);
    float v2 = (sq - (float)HID * m2 * m2) * (1.0f / (HID - 1));
    const float s2 = 1.0f / (sqrtf(v2) + 1e-6f);

    // ---------------- Phase 3: basis2 + GEMM2 on this thread's 32 h's ----------------
    float oacc[OUTD] = {0.f, 0.f, 0.f, 0.f, 0.f};
    #pragma unroll 4
    for (int j = 0; j < 32; j++) {
        float xn = (h[j] - m2) * s2;
        int jj = oh * 32 + j;
        #pragma unroll
        for (int n = 0; n < NB; n++) {
            float d = xn - ctr[n];
            float e = __expf(K2 * d * d);
            #pragma unroll
            for (int q = 0; q < OUTD; q++)
                oacc[q] += e * c2s[q * (HID * NB) + jj * NB + n];  // broadcast read
        }
    }

    // combine pair partials
    float* part = red + 2 * NTHR;   // [128][5]
    #pragma unroll
    for (int q = 0; q < OUTD; q++) part[t * 5 + q] = oacc[q];
    __syncthreads();
    if (t < BM) {
        float* op = out + ((size_t)blk * BM + t) * OUTD;
        #pragma unroll
        for (int q = 0; q < OUTD; q++)
            op[q] = part[t * 5 + q] + part[(t + 64) * 5 + q];
    }
}

extern "C" void kernel_launch(void* const* d_in, const int* in_sizes, int n_in,
                              void* d_out, int out_size)
{
    const float* x       = (const float*)d_in[0];   // [65536,1000]
    const float* c1      = (const float*)d_in[1];   // [64,100,16]
    const float* c2      = (const float*)d_in[2];   // [5,64,16]
    const float* centers = (const float*)d_in[3];   // [16]
    float* out = (float*)d_out;

    cudaFuncSetAttribute(kan_fused_kernel,
                         cudaFuncAttributeMaxDynamicSharedMemorySize, SMEM_BYTES);
    kan_fused_kernel<<<BATCH / BM, NTHR, SMEM_BYTES>>>(x, c1, c2, centers, out);
}

// round 5
// speedup vs baseline: 2.2675x; 2.2675x over previous
#include <cuda_runtime.h>
#include <cuda_bf16.h>
#include <math.h>
#include <stdint.h>

// ---------------- problem constants ----------------
#define SEQ   1000
#define IND   100
#define HID   64
#define OUTD  5
#define NB    16
#define BATCH 65536

#define BM    128
#define NTHR  128
#define NCH1  25          // 1600 / 64
#define NCH2  16          // 1024 / 64

// exp(-0.5 d^2 / 0.36) = ex2(d^2 * C2L)
#define C2L  (-2.0037430569044415f)

// ---------------- smem layout (bytes) ----------------
// xp:  fp32 [100][128]            = 51200   (reused as hs fp32 [128][65] = 33280)
// A tiles bf16 [128][72]  hi/lo   = 18432 each   (row stride 144 B)
// B1 tiles bf16 [64][72]  hi/lo   = 9216 each
// B2 tiles bf16 [8][72]   hi/lo   = 1152 each
#define OFF_XP 0
#define OFF_AH 51200
#define OFF_AL (OFF_AH + 18432)
#define OFF_BH (OFF_AL + 18432)
#define OFF_BL (OFF_BH + 9216)
#define OFF_CH (OFF_BL + 9216)
#define OFF_CL (OFF_CH + 1152)
#define SMEM_BYTES (OFF_CL + 1152)

// pre-split, pre-padded weight images (match smem layout exactly)
__device__ __align__(16) unsigned char g_c1h[NCH1 * 9216];
__device__ __align__(16) unsigned char g_c1l[NCH1 * 9216];
__device__ __align__(16) unsigned char g_c2h[NCH2 * 1152];
__device__ __align__(16) unsigned char g_c2l[NCH2 * 1152];

// ---------------- helpers ----------------
__device__ __forceinline__ uint32_t smem_u32(const void* p) {
    uint32_t a;
    asm("{ .reg .u64 t; cvta.to.shared.u64 t, %1; cvt.u32.u64 %0, t; }" : "=r"(a) : "l"(p));
    return a;
}
__device__ __forceinline__ float ex2f(float x) {
    float r; asm("ex2.approx.ftz.f32 %0, %1;" : "=f"(r) : "f"(x)); return r;
}
// pack (lo, hi) floats -> bf16x2 (lo in low half)
__device__ __forceinline__ uint32_t pk_bf2(float lo, float hi) {
    uint32_t r; asm("cvt.rn.bf16x2.f32 %0, %1, %2;" : "=r"(r) : "f"(hi), "f"(lo)); return r;
}
__device__ __forceinline__ float bf_lo(uint32_t u) { return __uint_as_float(u << 16); }
__device__ __forceinline__ float bf_hi(uint32_t u) { return __uint_as_float(u & 0xffff0000u); }

__device__ __forceinline__ void ldsm4(uint32_t* r, uint32_t addr) {
    asm volatile("ldmatrix.sync.aligned.m8n8.x4.shared.b16 {%0,%1,%2,%3}, [%4];"
                 : "=r"(r[0]), "=r"(r[1]), "=r"(r[2]), "=r"(r[3]) : "r"(addr));
}
__device__ __forceinline__ void ldsm2(uint32_t* r, uint32_t addr) {
    asm volatile("ldmatrix.sync.aligned.m8n8.x2.shared.b16 {%0,%1}, [%2];"
                 : "=r"(r[0]), "=r"(r[1]) : "r"(addr));
}
__device__ __forceinline__ void mma_bf16(float* d, const uint32_t* a, const uint32_t* b) {
    asm volatile(
        "mma.sync.aligned.m16n8k16.row.col.f32.bf16.bf16.f32 "
        "{%0,%1,%2,%3}, {%4,%5,%6,%7}, {%8,%9}, {%0,%1,%2,%3};"
        : "+f"(d[0]), "+f"(d[1]), "+f"(d[2]), "+f"(d[3])
        : "r"(a[0]), "r"(a[1]), "r"(a[2]), "r"(a[3]), "r"(b[0]), "r"(b[1]));
}

// 16 RBF values for one x -> 8 packed hi words + 8 packed lo words
__device__ __forceinline__ void basis16(float xn, const float* ctr,
                                        uint32_t* hp, uint32_t* lp) {
#pragma unroll
    for (int q = 0; q < 8; q++) {
        float d0 = xn - ctr[2 * q];
        float d1 = xn - ctr[2 * q + 1];
        float e0 = ex2f(d0 * d0 * C2L);
        float e1 = ex2f(d1 * d1 * C2L);
        uint32_t h = pk_bf2(e0, e1);
        hp[q] = h;
        lp[q] = pk_bf2(e0 - bf_lo(h), e1 - bf_hi(h));
    }
}

// ---------------- prep: split c1/c2 to bf16 hi/lo in padded [n][72k] rows ----------------
__global__ void prep_kernel(const float* __restrict__ c1, const float* __restrict__ c2) {
    int tid = blockIdx.x * blockDim.x + threadIdx.x;
    int nth = gridDim.x * blockDim.x;
    // c1: [64 o][1600 k]
    for (int idx = tid; idx < 64 * 1600; idx += nth) {
        int o = idx / 1600, k = idx - o * 1600;
        int ch = k >> 6, kk = k & 63;
        float v = c1[idx];
        float hf = __bfloat162float(__float2bfloat16(v));
        size_t d = (size_t)ch * 9216 + o * 144 + kk * 2;
        *(__nv_bfloat16*)(g_c1h + d) = __float2bfloat16(hf);
        *(__nv_bfloat16*)(g_c1l + d) = __float2bfloat16(v - hf);
    }
    // c2: [8 o padded][1024 k]
    for (int idx = tid; idx < 8 * 1024; idx += nth) {
        int o = idx >> 10, k = idx & 1023;
        int ch = k >> 6, kk = k & 63;
        float v = (o < OUTD) ? c2[o * 1024 + k] : 0.0f;
        float hf = __bfloat162float(__float2bfloat16(v));
        size_t d = (size_t)ch * 1152 + o * 144 + kk * 2;
        *(__nv_bfloat16*)(g_c2h + d) = __float2bfloat16(hf);
        *(__nv_bfloat16*)(g_c2l + d) = __float2bfloat16(v - hf);
    }
}

// ---------------- main kernel ----------------
__global__ __launch_bounds__(NTHR, 2)
void kan_main(const float* __restrict__ x,
              const float* __restrict__ centers,
              float* __restrict__ out)
{
    extern __shared__ unsigned char smem[];
    const uint32_t sbase = smem_u32(smem);
    const int t = threadIdx.x, blk = blockIdx.x;
    const int l = t & 31, w = t >> 5;
    float* xp = (float*)(smem + OFF_XP);

    float ctr[NB];
#pragma unroll
    for (int n = 0; n < NB; n++) ctr[n] = __ldg(centers + n);

    // ---------- phase 1: pool 1000 -> 100 into xp[i][row] ----------
    const float* xblk = x + (size_t)blk * BM * SEQ;
#pragma unroll 2
    for (int p = t; p < BM * IND; p += NTHR) {
        int row = p / IND;
        int i = p - row * IND;
        const float2* xr = (const float2*)(xblk + row * SEQ + i * 10);
        float s = 0.f;
#pragma unroll
        for (int m = 0; m < 5; m++) { float2 v = __ldg(xr + m); s += v.x + v.y; }
        xp[i * BM + row] = s * 0.1f;
    }
    __syncthreads();

    // row stats (thread t = row t): two-pass, ddof=1, eps outside sqrt
    float mu = 0.f;
#pragma unroll 10
    for (int i = 0; i < IND; i++) mu += xp[i * BM + t];
    mu *= (1.0f / IND);
    float var = 0.f;
#pragma unroll 10
    for (int i = 0; i < IND; i++) { float d = xp[i * BM + t] - mu; var += d * d; }
    var *= (1.0f / (IND - 1));
    const float sc = 1.0f / (sqrtf(var) + 1e-6f);

    // lane-dependent ldmatrix offsets (row stride 144 B)
    const uint32_t aoff = ((l & 7) + ((l >> 3) & 1) * 8) * 144 + (l >> 4) * 16;
    const uint32_t boff = ((l & 7) + (l >> 4) * 8) * 144 + ((l >> 3) & 1) * 16;
    const uint32_t coff = ((l & 15) & 7) * 144 + (((l & 15) >> 3) & 1) * 16;
    const uint32_t sAH = sbase + OFF_AH, sAL = sbase + OFF_AL;
    const uint32_t sBH = sbase + OFF_BH, sBL = sbase + OFF_BL;
    const uint32_t sCH = sbase + OFF_CH, sCL = sbase + OFF_CL;

    // ---------- GEMM1: 25 chunks of K=64, 3-pass bf16 ----------
    float acc[2][8][4];
#pragma unroll
    for (int mt = 0; mt < 2; mt++)
#pragma unroll
        for (int nt = 0; nt < 8; nt++)
#pragma unroll
            for (int q = 0; q < 4; q++) acc[mt][nt][q] = 0.f;

#pragma unroll 1
    for (int ch = 0; ch < NCH1; ch++) {
        __syncthreads();
        // copy B1 tiles (9216 B hi + lo = 576 uint4 each)
        {
            const uint4* gh = (const uint4*)(g_c1h + (size_t)ch * 9216);
            const uint4* gl = (const uint4*)(g_c1l + (size_t)ch * 9216);
            uint4* dh = (uint4*)(smem + OFF_BH);
            uint4* dl = (uint4*)(smem + OFF_BL);
#pragma unroll
            for (int j = 0; j < 4; j++) {
                dh[j * NTHR + t] = __ldg(gh + j * NTHR + t);
                dl[j * NTHR + t] = __ldg(gl + j * NTHR + t);
            }
            if (t < 64) { dh[512 + t] = __ldg(gh + 512 + t); dl[512 + t] = __ldg(gl + 512 + t); }
        }
        // A tile: thread t = row t, 4 x's x 16 basis
#pragma unroll
        for (int ii = 0; ii < 4; ii++) {
            float xn = (xp[(ch * 4 + ii) * BM + t] - mu) * sc;
            uint32_t hp[8], lp[8];
            basis16(xn, ctr, hp, lp);
            *(uint4*)(smem + OFF_AH + t * 144 + ii * 32)      = make_uint4(hp[0], hp[1], hp[2], hp[3]);
            *(uint4*)(smem + OFF_AH + t * 144 + ii * 32 + 16) = make_uint4(hp[4], hp[5], hp[6], hp[7]);
            *(uint4*)(smem + OFF_AL + t * 144 + ii * 32)      = make_uint4(lp[0], lp[1], lp[2], lp[3]);
            *(uint4*)(smem + OFF_AL + t * 144 + ii * 32 + 16) = make_uint4(lp[4], lp[5], lp[6], lp[7]);
        }
        __syncthreads();

#pragma unroll
        for (int ks = 0; ks < 4; ks++) {
            uint32_t ah[2][4], al[2][4], bb[4][4];
#pragma unroll
            for (int mt = 0; mt < 2; mt++) {
                uint32_t rb = (w * 32 + mt * 16) * 144 + ks * 32 + aoff;
                ldsm4(ah[mt], sAH + rb);
                ldsm4(al[mt], sAL + rb);
            }
#pragma unroll
            for (int p = 0; p < 4; p++) ldsm4(bb[p], sBH + p * 16 * 144 + ks * 32 + boff);
#pragma unroll
            for (int mt = 0; mt < 2; mt++)
#pragma unroll
                for (int nt = 0; nt < 8; nt++)
                    mma_bf16(acc[mt][nt], ah[mt], &bb[nt >> 1][(nt & 1) * 2]);
#pragma unroll
            for (int mt = 0; mt < 2; mt++)
#pragma unroll
                for (int nt = 0; nt < 8; nt++)
                    mma_bf16(acc[mt][nt], al[mt], &bb[nt >> 1][(nt & 1) * 2]);
#pragma unroll
            for (int p = 0; p < 4; p++) ldsm4(bb[p], sBL + p * 16 * 144 + ks * 32 + boff);
#pragma unroll
            for (int mt = 0; mt < 2; mt++)
#pragma unroll
                for (int nt = 0; nt < 8; nt++)
                    mma_bf16(acc[mt][nt], ah[mt], &bb[nt >> 1][(nt & 1) * 2]);
        }
    }

    // ---------- epilogue 1: tanh -> hs[row][65] ----------
    __syncthreads();
    float* hs = (float*)(smem + OFF_XP);
#pragma unroll
    for (int mt = 0; mt < 2; mt++)
#pragma unroll
        for (int nt = 0; nt < 8; nt++) {
            int r0 = w * 32 + mt * 16 + (l >> 2);
            int c  = nt * 8 + (l & 3) * 2;
            hs[r0 * 65 + c]           = tanhf(acc[mt][nt][0]);
            hs[r0 * 65 + c + 1]       = tanhf(acc[mt][nt][1]);
            hs[(r0 + 8) * 65 + c]     = tanhf(acc[mt][nt][2]);
            hs[(r0 + 8) * 65 + c + 1] = tanhf(acc[mt][nt][3]);
        }
    __syncthreads();

    // norm2 stats for row t (two-pass, ddof=1)
    float m2 = 0.f;
#pragma unroll 8
    for (int j = 0; j < HID; j++) m2 += hs[t * 65 + j];
    m2 *= (1.0f / HID);
    float v2 = 0.f;
#pragma unroll 8
    for (int j = 0; j < HID; j++) { float d = hs[t * 65 + j] - m2; v2 += d * d; }
    v2 *= (1.0f / (HID - 1));
    const float s2 = 1.0f / (sqrtf(v2) + 1e-6f);

    // ---------- GEMM2: 16 chunks of K=64, N=8 (5 valid) ----------
    float a2[2][4];
#pragma unroll
    for (int mt = 0; mt < 2; mt++)
#pragma unroll
        for (int q = 0; q < 4; q++) a2[mt][q] = 0.f;

#pragma unroll 1
    for (int ch2 = 0; ch2 < NCH2; ch2++) {
        __syncthreads();
        if (t < 72)
            ((uint4*)(smem + OFF_CH))[t] = __ldg((const uint4*)(g_c2h + (size_t)ch2 * 1152) + t);
        else if (t < 144)
            ((uint4*)(smem + OFF_CL))[t - 72] = __ldg((const uint4*)(g_c2l + (size_t)ch2 * 1152) + (t - 72));
#pragma unroll
        for (int ii = 0; ii < 4; ii++) {
            float xn = (hs[t * 65 + ch2 * 4 + ii] - m2) * s2;
            uint32_t hp[8], lp[8];
            basis16(xn, ctr, hp, lp);
            *(uint4*)(smem + OFF_AH + t * 144 + ii * 32)      = make_uint4(hp[0], hp[1], hp[2], hp[3]);
            *(uint4*)(smem + OFF_AH + t * 144 + ii * 32 + 16) = make_uint4(hp[4], hp[5], hp[6], hp[7]);
            *(uint4*)(smem + OFF_AL + t * 144 + ii * 32)      = make_uint4(lp[0], lp[1], lp[2], lp[3]);
            *(uint4*)(smem + OFF_AL + t * 144 + ii * 32 + 16) = make_uint4(lp[4], lp[5], lp[6], lp[7]);
        }
        __syncthreads();

#pragma unroll
        for (int ks = 0; ks < 4; ks++) {
            uint32_t ah[2][4], al[2][4], b2h[2], b2l[2];
#pragma unroll
            for (int mt = 0; mt < 2; mt++) {
                uint32_t rb = (w * 32 + mt * 16) * 144 + ks * 32 + aoff;
                ldsm4(ah[mt], sAH + rb);
                ldsm4(al[mt], sAL + rb);
            }
            ldsm2(b2h, sCH + ks * 32 + coff);
            ldsm2(b2l, sCL + ks * 32 + coff);
#pragma unroll
            for (int mt = 0; mt < 2; mt++) {
                mma_bf16(a2[mt], ah[mt], b2h);
                mma_bf16(a2[mt], al[mt], b2h);
                mma_bf16(a2[mt], ah[mt], b2l);
            }
        }
    }

    // ---------- epilogue 2: write out (cols < 5) ----------
    {
        int c = (l & 3) * 2;
        size_t gr = (size_t)blk * BM;
#pragma unroll
        for (int mt = 0; mt < 2; mt++) {
            int r = w * 32 + mt * 16 + (l >> 2);
            if (c < OUTD)     out[(gr + r) * OUTD + c]     = a2[mt][0];
            if (c + 1 < OUTD) out[(gr + r) * OUTD + c + 1] = a2[mt][1];
            if (c < OUTD)     out[(gr + r + 8) * OUTD + c]     = a2[mt][2];
            if (c + 1 < OUTD) out[(gr + r + 8) * OUTD + c + 1] = a2[mt][3];
        }
    }
}

// ---------------- launch ----------------
extern "C" void kernel_launch(void* const* d_in, const int* in_sizes, int n_in,
                              void* d_out, int out_size)
{
    const float* x       = (const float*)d_in[0];   // [65536,1000]
    const float* c1      = (const float*)d_in[1];   // [64,100,16]
    const float* c2      = (const float*)d_in[2];   // [5,64,16]
    const float* centers = (const float*)d_in[3];   // [16]
    float* out = (float*)d_out;

    prep_kernel<<<128, 256>>>(c1, c2);

    cudaFuncSetAttribute(kan_main, cudaFuncAttributeMaxDynamicSharedMemorySize, SMEM_BYTES);
    kan_main<<<BATCH / BM, NTHR, SMEM_BYTES>>>(x, centers, out);
}